// round 2
// baseline (speedup 1.0000x reference)
#include <cuda_runtime.h>

// SpanRepLayer: start / inner-maxpool / end span representations.
// B=2, NS=512, S=1024, H=128. Output (B, NS, 3H) fp32.
//
// Inputs (metadata order):
//   d_in[0]: token_reps (B, S, H)  float32
//   d_in[1]: span_ids   (B, NS, 2) int32   [start, end+1]
//   d_in[2]: span_masks (B, NS)    int32 (bool promoted)
// Output: (B, NS, 3H) float32

#define SRL_B  2
#define SRL_NS 512
#define SRL_S  1024
#define SRL_H  128           // 32 float4 per token row
#define SRL_NSPANS (SRL_B * SRL_NS)
#define NEG_LIMIT -1e9f

__global__ __launch_bounds__(128) void span_rep_kernel(
    const float* __restrict__ token_reps,
    const int* __restrict__ span_ids,
    const int* __restrict__ span_masks,
    float* __restrict__ out)
{
    const int span = blockIdx.x * 4 + (threadIdx.x >> 5);  // 4 warps/block, 1 span/warp
    const int lane = threadIdx.x & 31;
    if (span >= SRL_NSPANS) return;

    float4* o = reinterpret_cast<float4*>(out) + (size_t)span * 96;  // 3H = 384 f32 = 96 f4

    if (!span_masks[span]) {
        const float4 z = make_float4(0.f, 0.f, 0.f, 0.f);
        o[lane] = z;
        o[lane + 32] = z;
        o[lane + 64] = z;
        return;
    }

    const int b = span / SRL_NS;
    const int start = span_ids[2 * span];
    const int end   = span_ids[2 * span + 1] - 1;   // inclusive

    const float4* __restrict__ base =
        reinterpret_cast<const float4*>(token_reps) + (size_t)b * SRL_S * 32;

    const float4 sr = base[start * 32 + lane];
    const float4 er = base[end * 32 + lane];

    float4 inner;
    if (end - 1 >= start + 1) {
        inner = make_float4(NEG_LIMIT, NEG_LIMIT, NEG_LIMIT, NEG_LIMIT);
        #pragma unroll 4
        for (int t = start + 1; t <= end - 1; ++t) {
            const float4 v = base[t * 32 + lane];
            inner.x = fmaxf(inner.x, v.x);
            inner.y = fmaxf(inner.y, v.y);
            inner.z = fmaxf(inner.z, v.z);
            inner.w = fmaxf(inner.w, v.w);
        }
    } else {
        inner = sr;   // no inner tokens -> fall back to start rep
    }

    o[lane]      = sr;
    o[lane + 32] = inner;
    o[lane + 64] = er;
}

extern "C" void kernel_launch(void* const* d_in, const int* in_sizes, int n_in,
                              void* d_out, int out_size)
{
    const float* token_reps  = (const float*)d_in[0];
    const int* span_ids      = (const int*)d_in[1];
    const int* span_masks    = (const int*)d_in[2];
    float* out               = (float*)d_out;

    const int nblocks = (SRL_NSPANS + 3) / 4;  // 256
    span_rep_kernel<<<nblocks, 128>>>(token_reps, span_ids, span_masks, out);
}